// round 1
// baseline (speedup 1.0000x reference)
#include <cuda_runtime.h>

#define NPTS 100000
#define CDIM 64

// Scratch (device globals — no allocations allowed in kernel_launch)
__device__ float g_q[NPTS * CDIM];
__device__ float g_k[NPTS * CDIM];
__device__ float g_v[NPTS * CDIM];
__device__ float g_a[NPTS * CDIM];

typedef unsigned long long u64;

__device__ __forceinline__ u64 pack2(float lo, float hi) {
    u64 r;
    asm("mov.b64 %0, {%1, %2};" : "=l"(r) : "f"(lo), "f"(hi));
    return r;
}
__device__ __forceinline__ void unpack2(u64 v, float& lo, float& hi) {
    asm("mov.b64 {%0, %1}, %2;" : "=f"(lo), "=f"(hi) : "l"(v));
}
// d = a * b + d (elementwise on packed f32x2) — FFMA2, only reachable via PTX
__device__ __forceinline__ void fma2(u64& d, u64 a, u64 b) {
    asm("fma.rn.f32x2 %0, %1, %2, %0;" : "+l"(d) : "l"(a), "l"(b));
}

// ---------------------------------------------------------------------------
// Kernel 1: fused q/k/v projection.  [N,64] @ [64,192] (Wq|Wk|Wv columns).
// Block tile: 64 rows x 192 cols. Thread tile: 8 rows x 3 col-pairs (f32x2).
// feats tile resident in smem (16KB); W streamed in 16-row slabs (12KB).
// ---------------------------------------------------------------------------
__global__ __launch_bounds__(256) void qkv_kernel(
    const float* __restrict__ feats,
    const float* __restrict__ Wq,
    const float* __restrict__ Wk,
    const float* __restrict__ Wv,
    int N)
{
    __shared__ __align__(16) float sF[64 * 64];   // feats tile
    __shared__ __align__(16) float sW[16 * 192];  // W slab (16 k-rows x 192 cols)

    const int tid  = threadIdx.x;
    const int row0 = blockIdx.x * 64;

    // Load feats tile (64 rows x 64 cols, contiguous region)
    if (row0 + 64 <= N) {
        const float4* src = (const float4*)(feats + (size_t)row0 * 64);
        float4* dst = (float4*)sF;
#pragma unroll
        for (int t = 0; t < 4; t++) dst[tid + 256 * t] = src[tid + 256 * t];
    } else {
        for (int t = tid; t < 64 * 64; t += 256) {
            int r = t >> 6;
            sF[t] = (row0 + r < N) ? feats[(size_t)(row0 + r) * 64 + (t & 63)] : 0.f;
        }
    }

    const int ty = tid >> 5;   // 0..7 : row group (8 rows each)
    const int tx = tid & 31;   // 0..31: column pair (cols 2*tx, 2*tx+1 within each matrix)

    u64 acc[8][3];
#pragma unroll
    for (int r = 0; r < 8; r++)
#pragma unroll
        for (int j = 0; j < 3; j++) acc[r][j] = pack2(0.f, 0.f);

    for (int slab = 0; slab < 4; slab++) {
        __syncthreads();
        // Load W slab: rows i in [slab*16, slab*16+16), cols 0..191 = Wq|Wk|Wv
        for (int t = tid; t < 16 * 192; t += 256) {
            int ii = t / 192, c = t % 192;
            int gi = slab * 16 + ii;
            float w;
            if (c < 64)       w = Wq[gi * 64 + c];
            else if (c < 128) w = Wk[gi * 64 + (c - 64)];
            else              w = Wv[gi * 64 + (c - 128)];
            sW[t] = w;
        }
        __syncthreads();

#pragma unroll 4
        for (int ii = 0; ii < 16; ii++) {
            const int i = slab * 16 + ii;
            u64 f[8];
#pragma unroll
            for (int r = 0; r < 8; r++) {
                float fv = sF[(ty * 8 + r) * 64 + i];   // warp-uniform -> broadcast
                f[r] = pack2(fv, fv);
            }
#pragma unroll
            for (int j = 0; j < 3; j++) {
                u64 w = *(const u64*)&sW[ii * 192 + j * 64 + 2 * tx];  // LDS.64
#pragma unroll
                for (int r = 0; r < 8; r++) fma2(acc[r][j], w, f[r]);
            }
        }
    }

#pragma unroll
    for (int r = 0; r < 8; r++) {
        int row = row0 + ty * 8 + r;
        if (row < N) {
            float2 vq, vk, vv;
            unpack2(acc[r][0], vq.x, vq.y);
            unpack2(acc[r][1], vk.x, vk.y);
            unpack2(acc[r][2], vv.x, vv.y);
            size_t off = (size_t)row * 64 + 2 * tx;
            *(float2*)&g_q[off] = vq;
            *(float2*)&g_k[off] = vk;
            *(float2*)&g_v[off] = vv;
        }
    }
}

// ---------------------------------------------------------------------------
// Kernel 2: KNN attention. One thread per (point, head).
// Warp = 4 points x 8 heads -> each 256B neighbor row is fully coalesced.
// knn indices distributed across the 8-thread head group via shuffle.
// ---------------------------------------------------------------------------
__global__ __launch_bounds__(256) void attn_kernel(const int* __restrict__ knn, int N)
{
    const int g = blockIdx.x * 256 + threadIdx.x;
    int n = g >> 3;
    const int h = g & 7;
    const bool valid = (n < N);
    if (n >= N) n = N - 1;   // clamp so all lanes stay active for shuffles

    const int lane = threadIdx.x & 31;
    const int base = lane & 24;   // first lane of this point's 8-thread group

    // Each of the 8 threads holds 2 of the 16 neighbor indices
    const int my0 = knn[(size_t)n * 16 + h * 2];
    const int my1 = knn[(size_t)n * 16 + h * 2 + 1];

    const float* qp = g_q + (size_t)n * 64 + h * 8;
    const float4 q0 = *(const float4*)qp;
    const float4 q1 = *(const float4*)(qp + 4);

    int   idx[16];
    float s[16];
#pragma unroll
    for (int k = 0; k < 16; k++) {
        int v = (k & 1) ? my1 : my0;
        idx[k] = __shfl_sync(0xffffffffu, v, base + (k >> 1));
    }

#pragma unroll
    for (int k = 0; k < 16; k++) {
        const float* kp = g_k + (size_t)idx[k] * 64 + h * 8;
        const float4 a = *(const float4*)kp;
        const float4 b = *(const float4*)(kp + 4);
        float d = q0.x * a.x + q0.y * a.y + q0.z * a.z + q0.w * a.w
                + q1.x * b.x + q1.y * b.y + q1.z * b.z + q1.w * b.w;
        s[k] = d * 0.3535533905932738f;   // 1/sqrt(8)
    }

    // softmax over 16 neighbors (in registers)
    float m = s[0];
#pragma unroll
    for (int k = 1; k < 16; k++) m = fmaxf(m, s[k]);
    float sum = 0.f;
#pragma unroll
    for (int k = 0; k < 16; k++) { s[k] = __expf(s[k] - m); sum += s[k]; }
    const float inv = 1.0f / sum;

    float o[8];
#pragma unroll
    for (int d = 0; d < 8; d++) o[d] = 0.f;
#pragma unroll
    for (int k = 0; k < 16; k++) {
        const float* vp = g_v + (size_t)idx[k] * 64 + h * 8;
        const float4 a = *(const float4*)vp;
        const float4 b = *(const float4*)(vp + 4);
        const float p = s[k];
        o[0] += p * a.x; o[1] += p * a.y; o[2] += p * a.z; o[3] += p * a.w;
        o[4] += p * b.x; o[5] += p * b.y; o[6] += p * b.z; o[7] += p * b.w;
    }

    if (valid) {
        float4 r0 = make_float4(o[0] * inv, o[1] * inv, o[2] * inv, o[3] * inv);
        float4 r1 = make_float4(o[4] * inv, o[5] * inv, o[6] * inv, o[7] * inv);
        float* op = g_a + (size_t)n * 64 + h * 8;
        *(float4*)op       = r0;
        *(float4*)(op + 4) = r1;
    }
}

// ---------------------------------------------------------------------------
// Kernel 3: output projection. [N,64] @ Wo[64,64] + bo.
// ---------------------------------------------------------------------------
__global__ __launch_bounds__(256) void oproj_kernel(
    const float* __restrict__ Wo,
    const float* __restrict__ bo,
    float* __restrict__ out,
    int N)
{
    __shared__ __align__(16) float sF[64 * 64];
    __shared__ __align__(16) float sW[64 * 64];

    const int tid  = threadIdx.x;
    const int row0 = blockIdx.x * 64;

    // Load Wo fully (16KB)
    {
        const float4* src = (const float4*)Wo;
        float4* dst = (float4*)sW;
#pragma unroll
        for (int t = 0; t < 4; t++) dst[tid + 256 * t] = src[tid + 256 * t];
    }
    // Load attention-output tile
    if (row0 + 64 <= N) {
        const float4* src = (const float4*)(g_a + (size_t)row0 * 64);
        float4* dst = (float4*)sF;
#pragma unroll
        for (int t = 0; t < 4; t++) dst[tid + 256 * t] = src[tid + 256 * t];
    } else {
        for (int t = tid; t < 64 * 64; t += 256) {
            int r = t >> 6;
            sF[t] = (row0 + r < N) ? g_a[(size_t)(row0 + r) * 64 + (t & 63)] : 0.f;
        }
    }
    __syncthreads();

    const int ty = tid >> 5;
    const int tx = tid & 31;

    u64 acc[8];
#pragma unroll
    for (int r = 0; r < 8; r++) acc[r] = pack2(0.f, 0.f);

#pragma unroll 8
    for (int i = 0; i < 64; i++) {
        u64 w = *(const u64*)&sW[i * 64 + 2 * tx];
#pragma unroll
        for (int r = 0; r < 8; r++) {
            float fv = sF[(ty * 8 + r) * 64 + i];
            fma2(acc[r], w, pack2(fv, fv));
        }
    }

    const float b0 = bo[2 * tx];
    const float b1 = bo[2 * tx + 1];
#pragma unroll
    for (int r = 0; r < 8; r++) {
        int row = row0 + ty * 8 + r;
        if (row < N) {
            float2 v;
            unpack2(acc[r], v.x, v.y);
            v.x += b0; v.y += b1;
            *(float2*)&out[(size_t)row * 64 + 2 * tx] = v;
        }
    }
}

// ---------------------------------------------------------------------------
extern "C" void kernel_launch(void* const* d_in, const int* in_sizes, int n_in,
                              void* d_out, int out_size)
{
    const float* feats = (const float*)d_in[0];
    const int*   knn   = (const int*)d_in[1];
    const float* Wq    = (const float*)d_in[2];
    const float* Wk    = (const float*)d_in[3];
    const float* Wv    = (const float*)d_in[4];
    const float* Wo    = (const float*)d_in[5];
    const float* bo    = (const float*)d_in[6];
    float* out = (float*)d_out;

    const int N = in_sizes[0] / CDIM;
    const int gemm_blocks = (N + 63) / 64;
    const int attn_blocks = (N * 8 + 255) / 256;

    qkv_kernel<<<gemm_blocks, 256>>>(feats, Wq, Wk, Wv, N);
    attn_kernel<<<attn_blocks, 256>>>(knn, N);
    oproj_kernel<<<gemm_blocks, 256>>>(Wo, bo, out, N);
}